// round 16
// baseline (speedup 1.0000x reference)
#include <cuda_runtime.h>
#include <cstdint>

#define B_SZ    65536
#define HID_SZ  512
#define THREADS 256
#define NBLK    512        // 512 CTAs x 128 rows
#define MTILE   128
#define NCHUNK  16         // K = 1024 in chunks of 64
#define ASTRIDE 72         // f32 per A row (64 + 8 pad; stride%32==8 -> conflict-free LDS.64)
#define ZSTRIDE 36         // f32 per z row

typedef unsigned long long u64;

// ---------------- smem layout (bytes) ----------------
// phase1: A0 @0 (36864), A1 @36864 (->73728), W0 @73728 (9216), W1b @82944 (->92160)
// b2s @92160 (8192), b1 @100352 (128) -> 100480
// phase2 overlay: W2q f32 [4][512][8] @0 (65536), Z @65536 (18432 ->83968)
#define OFF_A0    0
#define OFF_A1    36864
#define OFF_W0    73728
#define OFF_W1B   82944
#define OFF_B2S   92160
#define OFF_B1    100352
#define OFF_W2Q   0
#define OFF_Z     65536
#define SMEM_TOTAL 100480

// ---------------- device globals (prep output) ----------------
__device__ __align__(16) float g_W1r[32 * 1024];   // W1 tf32-rounded, [gq][k]
__device__ __align__(16) float g_W2q[4 * 512 * 8]; // W2 tf32, [g][spos][q] (q innermost)
__device__ __align__(16) float g_b2p[4 * 512];     // b2 h-permuted, [g][spos]

// spos -> h permutation: s = spos>>3, j = spos&7
// h = (s>>1)*16 + (j>>1)*4 + (s&1)*2 + (j&1)
__device__ __forceinline__ int spos_to_h(int spos) {
    int s = spos >> 3, j = spos & 7;
    return ((s >> 1) << 4) + ((j >> 1) << 2) + ((s & 1) << 1) + (j & 1);
}

// ---------------- helpers ----------------
__device__ __forceinline__ uint32_t smem_u32(const void* p) {
    uint32_t a;
    asm("{ .reg .u64 t; cvta.to.shared.u64 t, %1; cvt.u32.u64 %0, t; }" : "=r"(a) : "l"(p));
    return a;
}
__device__ __forceinline__ float tanh_acc(float xv) {
    float s = __fdividef(1.0f, 1.0f + __expf(-2.0f * xv));
    return 2.0f * s - 1.0f;
}
__device__ __forceinline__ float tanh_fast(float xv) {
    float y; asm("tanh.approx.f32 %0, %1;" : "=f"(y) : "f"(xv)); return y;
}
__device__ __forceinline__ float sigm_fast(float xv) {
    return fmaf(tanh_fast(0.5f * xv), 0.5f, 0.5f);
}
__device__ __forceinline__ void lds64(uint32_t& lo, uint32_t& hi, uint32_t a) {
    asm volatile("ld.shared.v2.b32 {%0,%1}, [%2];" : "=r"(lo), "=r"(hi) : "r"(a));
}
__device__ __forceinline__ float tf32r(float v) {
    float r; asm("cvt.rna.tf32.f32 %0, %1;" : "=f"(r) : "f"(v)); return r;
}
#define CP16(dst, src) \
    asm volatile("cp.async.ca.shared.global [%0], [%1], 16;" :: "r"(dst), "l"(src))
#define CP_COMMIT()  asm volatile("cp.async.commit_group;" ::: "memory")
#define CP_WAIT1()   asm volatile("cp.async.wait_group 1;" ::: "memory")
#define CP_WAIT0()   asm volatile("cp.async.wait_group 0;" ::: "memory")

// NOTE: kslot->physical-k relabeling: kslot fk <-> phys 2fk, kslot fk+4 <-> phys 2fk+1.
// Valid because A and B use the same mapping and the K-sum is permutation-invariant.
__device__ __forceinline__ void mma_tf32(float* d, uint32_t a0, uint32_t a1,
                                         uint32_t a2, uint32_t a3,
                                         uint32_t b0, uint32_t b1) {
    asm volatile(
        "mma.sync.aligned.m16n8k8.row.col.f32.tf32.tf32.f32 "
        "{%0,%1,%2,%3}, {%4,%5,%6,%7}, {%8,%9}, {%0,%1,%2,%3};"
        : "+f"(d[0]), "+f"(d[1]), "+f"(d[2]), "+f"(d[3])
        : "r"(a0), "r"(a1), "r"(a2), "r"(a3), "r"(b0), "r"(b1));
}

// ---------------- prep: tf32-round W1; W2 -> [g][spos][q]; permute b2 ----------------
__global__ void prep_kernel(const float* __restrict__ W1, const float* __restrict__ W2,
                            const float* __restrict__ b2) {
    int t = blockIdx.x * blockDim.x + threadIdx.x;
    if (t < 32 * 1024) {
        g_W1r[t] = tf32r(W1[t]);                           // [gq][k] flat
    } else if (t < 32 * 1024 + 16384) {
        int t2 = t - 32 * 1024;
        int g = t2 >> 12, spos = (t2 >> 3) & 511, q = t2 & 7;
        g_W2q[t2] = tf32r(W2[g * 4096 + spos_to_h(spos) * 8 + q]);   // src W2[g][h][q]
    } else if (t < 32 * 1024 + 16384 + 2048) {
        int t3 = t - (32 * 1024 + 16384);
        int g = t3 >> 9, spos = t3 & 511;
        g_b2p[t3] = b2[g * 512 + spos_to_h(spos)];
    }
}

// ---------------- main fused kernel ----------------
__global__ __launch_bounds__(THREADS, 2)
void lstm_kernel(const float* __restrict__ x, const float* __restrict__ h,
                 const float* __restrict__ c, const float* __restrict__ b1,
                 float* __restrict__ out) {
    extern __shared__ __align__(16) char smem[];
    const uint32_t sb = smem_u32(smem);
    const int tid = threadIdx.x;
    const int wid = tid >> 5, lid = tid & 31;
    const size_t row0 = (size_t)blockIdx.x * MTILE;

    // b2s (permuted) + b1s live outside all staging regions — load once
    ((uint4*)(smem + OFF_B2S))[tid]       = ((const uint4*)g_b2p)[tid];
    ((uint4*)(smem + OFF_B2S))[tid + 256] = ((const uint4*)g_b2p)[tid + 256];
    if (tid < 32) ((float*)(smem + OFF_B1))[tid] = b1[tid];

    // ---- cp.async chunk issuer: A (x/h, 128x64 f32) + W1 (32x64 f32) ----
    auto issue_chunk = [&](int ck) {
        uint32_t ab = sb + ((ck & 1) ? OFF_A1 : OFF_A0);
        uint32_t wb = sb + ((ck & 1) ? OFF_W1B : OFF_W0);
        const float* src = ((ck < 8) ? x : h) + row0 * 512 + (size_t)(ck & 7) * 64;
        #pragma unroll
        for (int j = 0; j < 8; j++) {
            int i = tid + j * THREADS;
            int r = i >> 4, s = i & 15;
            CP16(ab + (uint32_t)(r * (ASTRIDE * 4) + s * 16),
                 (const char*)(src + (size_t)r * 512) + s * 16);
        }
        const float* wsrc = g_W1r + (size_t)(ck) * 64;
        #pragma unroll
        for (int j = 0; j < 2; j++) {
            int i = tid + j * THREADS;
            int n = i >> 4, s = i & 15;
            CP16(wb + (uint32_t)(n * (ASTRIDE * 4) + s * 16),
                 (const char*)(wsrc + (size_t)n * 1024) + s * 16);
        }
        CP_COMMIT();
    };

    // ================= phase 1: GEMM1 via mma.sync tf32, LDS.64 frags =================
    float d[4][4];
    #pragma unroll
    for (int nt = 0; nt < 4; nt++)
        #pragma unroll
        for (int j = 0; j < 4; j++) d[nt][j] = 0.0f;

    issue_chunk(0);

    const int fr = lid >> 2, fk = lid & 3;
    // pair base: phys k = 2*fk (pair 2fk, 2fk+1)
    const uint32_t aoff = (uint32_t)(((wid * 16 + fr) * ASTRIDE + fk * 2) * 4);
    const uint32_t boff = (uint32_t)((fr * ASTRIDE + fk * 2) * 4);

    #pragma unroll 1
    for (int ck = 0; ck < NCHUNK; ck++) {
        if (ck + 1 < NCHUNK) { issue_chunk(ck + 1); CP_WAIT1(); }
        else                 { CP_WAIT0(); }
        __syncthreads();

        const uint32_t ab = sb + ((ck & 1) ? OFF_A1 : OFF_A0);
        const uint32_t wb = sb + ((ck & 1) ? OFF_W1B : OFF_W0);
        const uint32_t abase = ab + aoff;
        const uint32_t bbase = wb + boff;

        #pragma unroll
        for (int ks = 0; ks < 8; ks++) {
            uint32_t a0, a1, a2, a3;
            lds64(a0, a2, abase + ks * 32);                          // (kslot fk, fk+4)
            lds64(a1, a3, abase + 8 * ASTRIDE * 4 + ks * 32);
            #pragma unroll
            for (int nt = 0; nt < 4; nt++) {
                uint32_t b0, b1v;
                lds64(b0, b1v, bbase + (uint32_t)(nt * 8 * ASTRIDE * 4) + ks * 32);
                mma_tf32(d[nt], a0, a1, a2, a3, b0, b1v);
            }
        }
        __syncthreads();
    }

    // ---- z epilogue: bias + tanh -> tf32-rounded f32 in Z; overlay W2q ----
    {
        const float* b1s = (const float*)(smem + OFF_B1);
        float* zsm = (float*)(smem + OFF_Z);
        int rb = wid * 16 + (lid >> 2);
        int cb = (lid & 3) * 2;
        #pragma unroll
        for (int nt = 0; nt < 4; nt++) {
            int c0 = nt * 8 + cb;
            float bA = b1s[c0], bB = b1s[c0 + 1];
            float2 zlo = make_float2(tf32r(tanh_acc(d[nt][0] + bA)),
                                     tf32r(tanh_acc(d[nt][1] + bB)));
            float2 zhi = make_float2(tf32r(tanh_acc(d[nt][2] + bA)),
                                     tf32r(tanh_acc(d[nt][3] + bB)));
            *(float2*)(zsm + rb * ZSTRIDE + c0)       = zlo;
            *(float2*)(zsm + (rb + 8) * ZSTRIDE + c0) = zhi;
        }
        // W2q overlay: dense [g][spos][q], 65536 B = 4096 uint4, straight copy
        uint4* dw = (uint4*)(smem + OFF_W2Q);
        const uint4* swv = (const uint4*)g_W2q;
        #pragma unroll
        for (int j = 0; j < 16; j++) {
            int i = tid + j * THREADS;
            dw[i] = swv[i];
        }
    }
    __syncthreads();

    // ========== phase 2: GEMM2 tf32 (K=8), paired subtiles, LDS.64 frags ==========
    const float* b2s = (const float*)(smem + OFF_B2S);
    const int lr = lid >> 2;
    const int rbase = wid * 16;

    // A fragments (z): 4 gates x 4 regs, loaded ONCE; q-pairs (2fk, 2fk+1)
    uint32_t za[4][4];
    #pragma unroll
    for (int g = 0; g < 4; g++) {
        uint32_t base = sb + OFF_Z + (uint32_t)((((rbase + lr) * ZSTRIDE) + g * 8 + fk * 2) * 4);
        lds64(za[g][0], za[g][2], base);
        lds64(za[g][1], za[g][3], base + 8 * ZSTRIDE * 4);
    }

    const size_t r0g = row0 + rbase + lr;       // global row for frag row-low
    const float* c0p = c + r0g * HID_SZ;
    float* ho = out + r0g * HID_SZ;
    float* co = out + (size_t)B_SZ * HID_SZ + r0g * HID_SZ;

    #pragma unroll 1
    for (int p = 0; p < 32; p++) {
        const int sposA = p * 16;               // subtile 2p   (spos space)
        const int sposB = sposA + 8;            // subtile 2p+1
        const int hlane = p * 16 + fk * 4;      // 4 contiguous h owned by this lane

        // coalesced c loads (rows lo / hi)
        float4 cva = *(const float4*)(c0p + hlane);
        float4 cvb = *(const float4*)(c0p + 8 * HID_SZ + hlane);

        float dgA[4][4], dgB[4][4];
        #pragma unroll
        for (int g = 0; g < 4; g++) {
            float2 bA = *(const float2*)(b2s + g * 512 + sposA + fk * 2);
            float2 bB = *(const float2*)(b2s + g * 512 + sposB + fk * 2);
            dgA[g][0] = bA.x; dgA[g][1] = bA.y; dgA[g][2] = bA.x; dgA[g][3] = bA.y;
            dgB[g][0] = bB.x; dgB[g][1] = bB.y; dgB[g][2] = bB.x; dgB[g][3] = bB.y;
            // W2q: [g][spos][q]; lane takes q-pair (2fk,2fk+1) at n = spos+lr
            uint32_t wadr = sb + OFF_W2Q + (uint32_t)(g * 16384 + (sposA + lr) * 32 + fk * 8);
            uint32_t b0A, b1A, b0B, b1B;
            lds64(b0A, b1A, wadr);              // conflict-free
            lds64(b0B, b1B, wadr + 256);        // sposB = sposA + 8 rows of 32 B
            mma_tf32(dgA[g], za[g][0], za[g][1], za[g][2], za[g][3], b0A, b1A);
            mma_tf32(dgB[g], za[g][0], za[g][1], za[g][2], za[g][3], b0B, b1B);
        }

        // epilogue: h = hlane+{0,1} from A cols {0,1}, hlane+{2,3} from B cols {0,1}
        float hn_lo[4], cn_lo[4], hn_hi[4], cn_hi[4];
        {
            float ca_lo[4] = {cva.x, cva.y, cva.z, cva.w};
            float ca_hi[4] = {cvb.x, cvb.y, cvb.z, cvb.w};
            #pragma unroll
            for (int t = 0; t < 4; t++) {
                const int jc = t & 1;
                float (*dgX)[4] = (t < 2) ? dgA : dgB;
                {
                    float ig = sigm_fast(dgX[0][jc]);
                    float fg = sigm_fast(dgX[1][jc]);
                    float og = sigm_fast(dgX[2][jc]);
                    float gg = sigm_fast(dgX[3][jc]);
                    float cj = fmaf(fg, ca_lo[t], ig * gg);
                    cn_lo[t] = cj;
                    hn_lo[t] = og * tanh_fast(cj);
                }
                {
                    float ig = sigm_fast(dgX[0][jc + 2]);
                    float fg = sigm_fast(dgX[1][jc + 2]);
                    float og = sigm_fast(dgX[2][jc + 2]);
                    float gg = sigm_fast(dgX[3][jc + 2]);
                    float cj = fmaf(fg, ca_hi[t], ig * gg);
                    cn_hi[t] = cj;
                    hn_hi[t] = og * tanh_fast(cj);
                }
            }
        }
        *(float4*)(ho + hlane)              = make_float4(hn_lo[0], hn_lo[1], hn_lo[2], hn_lo[3]);
        *(float4*)(ho + 8 * HID_SZ + hlane) = make_float4(hn_hi[0], hn_hi[1], hn_hi[2], hn_hi[3]);
        *(float4*)(co + hlane)              = make_float4(cn_lo[0], cn_lo[1], cn_lo[2], cn_lo[3]);
        *(float4*)(co + 8 * HID_SZ + hlane) = make_float4(cn_hi[0], cn_hi[1], cn_hi[2], cn_hi[3]);
    }
}

extern "C" void kernel_launch(void* const* d_in, const int* in_sizes, int n_in,
                              void* d_out, int out_size) {
    const float* x  = (const float*)d_in[0];
    const float* h  = (const float*)d_in[1];
    const float* c  = (const float*)d_in[2];
    const float* W1 = (const float*)d_in[3];
    const float* b1 = (const float*)d_in[4];
    const float* W2 = (const float*)d_in[5];
    const float* b2 = (const float*)d_in[6];
    float* out = (float*)d_out;

    prep_kernel<<<200, 256>>>(W1, W2, b2);   // 51200 threads: 32768 W1 + 16384 W2q + 2048 b2

    cudaFuncSetAttribute(lstm_kernel, cudaFuncAttributeMaxDynamicSharedMemorySize, SMEM_TOTAL);
    lstm_kernel<<<NBLK, THREADS, SMEM_TOTAL>>>(x, h, c, b1, out);
}

// round 17
// speedup vs baseline: 1.6518x; 1.6518x over previous
#include <cuda_runtime.h>
#include <cstdint>

#define B_SZ    65536
#define HID_SZ  512
#define THREADS 256
#define NBLK    512        // 512 CTAs x 128 rows
#define MTILE   128
#define NCHUNK  16         // K = 1024 in chunks of 64
#define ASTRIDE 68         // f32 per A row (64 + 4 pad)
#define W2STRIDE 516       // f32 per W2 row; 516%32==4 -> q-rows 2fk/2fk+1 conflict-free

typedef unsigned long long u64;

// ---------------- smem layout (bytes) ----------------
// phase1: A0 @0 (34816), A1 @34816 (->69632), W0 @69632 (8704), W1b @78336 (->87040)
// b2s @87040 (8192), b1 @95232 (128)
// phase2 overlay: W2s f32 [32][516] @0 (66048, inside dead staging)
#define OFF_A0    0
#define OFF_A1    34816
#define OFF_W0    69632
#define OFF_W1B   78336
#define OFF_B2S   87040
#define OFF_B1    95232
#define OFF_W2S   0
#define SMEM_TOTAL 95360

// ---------------- device globals (prep output) ----------------
__device__ __align__(16) float g_W1r[32 * 1024];   // W1 tf32-rounded, [gq][k]
__device__ __align__(16) float g_W2t[32 * 512];    // W2 transposed+h-permuted tf32, [gq][spos]
__device__ __align__(16) float g_b2p[4 * 512];     // b2 h-permuted, [g][spos]

// spos -> h permutation: s = spos>>3, j = spos&7
// h = (s>>1)*16 + (j>>1)*4 + (s&1)*2 + (j&1)
__device__ __forceinline__ int spos_to_h(int spos) {
    int s = spos >> 3, j = spos & 7;
    return ((s >> 1) << 4) + ((j >> 1) << 2) + ((s & 1) << 1) + (j & 1);
}

// ---------------- helpers ----------------
__device__ __forceinline__ uint32_t smem_u32(const void* p) {
    uint32_t a;
    asm("{ .reg .u64 t; cvta.to.shared.u64 t, %1; cvt.u32.u64 %0, t; }" : "=r"(a) : "l"(p));
    return a;
}
__device__ __forceinline__ float tanh_acc(float xv) {
    float s = __fdividef(1.0f, 1.0f + __expf(-2.0f * xv));
    return 2.0f * s - 1.0f;
}
__device__ __forceinline__ float tanh_fast(float xv) {
    float y; asm("tanh.approx.f32 %0, %1;" : "=f"(y) : "f"(xv)); return y;
}
__device__ __forceinline__ float sigm_fast(float xv) {
    return fmaf(tanh_fast(0.5f * xv), 0.5f, 0.5f);
}
__device__ __forceinline__ uint32_t lds32(uint32_t a) {
    uint32_t v; asm volatile("ld.shared.b32 %0, [%1];" : "=r"(v) : "r"(a)); return v;
}
__device__ __forceinline__ float tf32r(float v) {
    float r; asm("cvt.rna.tf32.f32 %0, %1;" : "=f"(r) : "f"(v)); return r;
}
#define CP16(dst, src) \
    asm volatile("cp.async.ca.shared.global [%0], [%1], 16;" :: "r"(dst), "l"(src))
#define CP_COMMIT()  asm volatile("cp.async.commit_group;" ::: "memory")
#define CP_WAIT1()   asm volatile("cp.async.wait_group 1;" ::: "memory")
#define CP_WAIT0()   asm volatile("cp.async.wait_group 0;" ::: "memory")

// Phase-2 uses a kslot->phys-q relabel: kslot fk <-> q 2fk, kslot fk+4 <-> q 2fk+1.
// Valid since A and B agree on the mapping (K-sum permutation-invariant).
__device__ __forceinline__ void mma_tf32(float* d, uint32_t a0, uint32_t a1,
                                         uint32_t a2, uint32_t a3,
                                         uint32_t b0, uint32_t b1) {
    asm volatile(
        "mma.sync.aligned.m16n8k8.row.col.f32.tf32.tf32.f32 "
        "{%0,%1,%2,%3}, {%4,%5,%6,%7}, {%8,%9}, {%0,%1,%2,%3};"
        : "+f"(d[0]), "+f"(d[1]), "+f"(d[2]), "+f"(d[3])
        : "r"(a0), "r"(a1), "r"(a2), "r"(a3), "r"(b0), "r"(b1));
}

// ---------------- prep: tf32-round W1; transpose+permute W2; permute b2 ----------------
__global__ void prep_kernel(const float* __restrict__ W1, const float* __restrict__ W2,
                            const float* __restrict__ b2) {
    int t = blockIdx.x * blockDim.x + threadIdx.x;
    if (t < 32 * 1024) {
        g_W1r[t] = tf32r(W1[t]);                           // [gq][k] flat
    } else if (t < 32 * 1024 + 32 * 512) {
        int t2 = t - 32 * 1024;
        int gq = t2 >> 9, spos = t2 & 511;
        int g = gq >> 3, q = gq & 7;
        g_W2t[t2] = tf32r(W2[g * 4096 + spos_to_h(spos) * 8 + q]);   // src W2[g][h][q]
    } else if (t < 32 * 1024 + 32 * 512 + 4 * 512) {
        int t3 = t - (32 * 1024 + 32 * 512);
        int g = t3 >> 9, spos = t3 & 511;
        g_b2p[t3] = b2[g * 512 + spos_to_h(spos)];
    }
}

// ---------------- main fused kernel ----------------
__global__ __launch_bounds__(THREADS, 2)
void lstm_kernel(const float* __restrict__ x, const float* __restrict__ h,
                 const float* __restrict__ c, const float* __restrict__ b1,
                 float* __restrict__ out) {
    extern __shared__ __align__(16) char smem[];
    const uint32_t sb = smem_u32(smem);
    const int tid = threadIdx.x;
    const int wid = tid >> 5, lid = tid & 31;
    const size_t row0 = (size_t)blockIdx.x * MTILE;

    // b2s (permuted) + b1s live outside all staging regions — load once
    ((uint4*)(smem + OFF_B2S))[tid]       = ((const uint4*)g_b2p)[tid];
    ((uint4*)(smem + OFF_B2S))[tid + 256] = ((const uint4*)g_b2p)[tid + 256];
    if (tid < 32) ((float*)(smem + OFF_B1))[tid] = b1[tid];

    // ---- cp.async chunk issuer: A (x/h, 128x64 f32) + W1 (32x64 f32) ----
    auto issue_chunk = [&](int ck) {
        uint32_t ab = sb + ((ck & 1) ? OFF_A1 : OFF_A0);
        uint32_t wb = sb + ((ck & 1) ? OFF_W1B : OFF_W0);
        const float* src = ((ck < 8) ? x : h) + row0 * 512 + (size_t)(ck & 7) * 64;
        #pragma unroll
        for (int j = 0; j < 8; j++) {
            int i = tid + j * THREADS;
            int r = i >> 4, s = i & 15;
            CP16(ab + (uint32_t)(r * (ASTRIDE * 4) + s * 16),
                 (const char*)(src + (size_t)r * 512) + s * 16);
        }
        const float* wsrc = g_W1r + (size_t)(ck) * 64;
        #pragma unroll
        for (int j = 0; j < 2; j++) {
            int i = tid + j * THREADS;
            int n = i >> 4, s = i & 15;
            CP16(wb + (uint32_t)(n * (ASTRIDE * 4) + s * 16),
                 (const char*)(wsrc + (size_t)n * 1024) + s * 16);
        }
        CP_COMMIT();
    };

    // ================= phase 1: GEMM1 via mma.sync tf32 =================
    float d[4][4];
    #pragma unroll
    for (int nt = 0; nt < 4; nt++)
        #pragma unroll
        for (int j = 0; j < 4; j++) d[nt][j] = 0.0f;

    issue_chunk(0);

    const int fr = lid >> 2, fk = lid & 3;
    const uint32_t aoff = (uint32_t)(((wid * 16 + fr) * ASTRIDE + fk) * 4);
    const uint32_t boff = (uint32_t)((fr * ASTRIDE + fk) * 4);

    #pragma unroll 1
    for (int ck = 0; ck < NCHUNK; ck++) {
        if (ck + 1 < NCHUNK) { issue_chunk(ck + 1); CP_WAIT1(); }
        else                 { CP_WAIT0(); }
        __syncthreads();

        const uint32_t ab = sb + ((ck & 1) ? OFF_A1 : OFF_A0);
        const uint32_t wb = sb + ((ck & 1) ? OFF_W1B : OFF_W0);
        const uint32_t abase = ab + aoff;
        const uint32_t bbase = wb + boff;

        #pragma unroll
        for (int ks = 0; ks < 8; ks++) {
            const uint32_t ka = abase + ks * 32;
            uint32_t a0 = lds32(ka);
            uint32_t a1 = lds32(ka + 8 * ASTRIDE * 4);
            uint32_t a2 = lds32(ka + 16);
            uint32_t a3 = lds32(ka + 8 * ASTRIDE * 4 + 16);
            #pragma unroll
            for (int nt = 0; nt < 4; nt++) {
                const uint32_t kb = bbase + (uint32_t)(nt * 8 * ASTRIDE * 4) + ks * 32;
                uint32_t b0 = lds32(kb);
                uint32_t b1v = lds32(kb + 16);
                mma_tf32(d[nt], a0, a1, a2, a3, b0, b1v);
            }
        }
        __syncthreads();
    }

    // ---- z handoff IN REGISTERS: phase-1 D frag -> phase-2 A frag (relabeled k) ----
    // D layout: d[g][0]=(row fr, col g*8+2fk), d[g][1]=(fr, +1), d[g][2]=(fr+8, 2fk), d[g][3]=(fr+8, +1)
    // A frag (relabel kslot fk->q 2fk, fk+4->q 2fk+1):
    //   a0=(row lo, q 2fk)  a1=(row hi, q 2fk)  a2=(row lo, q 2fk+1)  a3=(row hi, q 2fk+1)
    uint32_t za[4][4];
    {
        const float* b1s = (const float*)(smem + OFF_B1);
        #pragma unroll
        for (int g = 0; g < 4; g++) {
            float bA = b1s[g * 8 + 2 * fk];
            float bB = b1s[g * 8 + 2 * fk + 1];
            za[g][0] = __float_as_uint(tf32r(tanh_acc(d[g][0] + bA)));
            za[g][1] = __float_as_uint(tf32r(tanh_acc(d[g][2] + bA)));
            za[g][2] = __float_as_uint(tf32r(tanh_acc(d[g][1] + bB)));
            za[g][3] = __float_as_uint(tf32r(tanh_acc(d[g][3] + bB)));
        }
    }

    // ---- overlay W2s onto dead staging: [32 gq][516] f32 ----
    {
        const uint4* swv = (const uint4*)g_W2t;
        #pragma unroll
        for (int j = 0; j < 16; j++) {
            int i = tid + j * THREADS;          // 4096 uint4
            int row = i >> 7, s = i & 127;      // 128 uint4 (512 f32) per source row
            *(uint4*)(smem + OFF_W2S + (uint32_t)((row * W2STRIDE + s * 4) * 4)) = swv[i];
        }
    }
    __syncthreads();

    // ========== phase 2: GEMM2 tf32 (K=8), paired subtiles, coalesced 16B I/O ==========
    const float* b2s = (const float*)(smem + OFF_B2S);
    const int lr = lid >> 2;

    const size_t r0g = row0 + wid * 16 + lr;    // global row for frag row-low
    const float* c0p = c + r0g * HID_SZ;
    float* ho = out + r0g * HID_SZ;
    float* co = out + (size_t)B_SZ * HID_SZ + r0g * HID_SZ;

    #pragma unroll 1
    for (int p = 0; p < 32; p++) {
        const int sposA = p * 16;               // subtile 2p   (spos space)
        const int sposB = sposA + 8;            // subtile 2p+1
        const int hlane = p * 16 + fk * 4;      // 4 contiguous h owned by this lane

        // coalesced c loads (rows lo / hi), early
        float4 cva = *(const float4*)(c0p + hlane);
        float4 cvb = *(const float4*)(c0p + 8 * HID_SZ + hlane);

        float dgA[4][4], dgB[4][4];
        #pragma unroll
        for (int g = 0; g < 4; g++) {
            float2 bA = *(const float2*)(b2s + g * 512 + sposA + fk * 2);
            float2 bB = *(const float2*)(b2s + g * 512 + sposB + fk * 2);
            dgA[g][0] = bA.x; dgA[g][1] = bA.y; dgA[g][2] = bA.x; dgA[g][3] = bA.y;
            dgB[g][0] = bB.x; dgB[g][1] = bB.y; dgB[g][2] = bB.x; dgB[g][3] = bB.y;
            // B operand: q-rows 2fk (b0) and 2fk+1 (b1), n = spos + lr; conflict-free (stride 516)
            uint32_t wb0 = sb + OFF_W2S + (uint32_t)(((g * 8 + 2 * fk) * W2STRIDE + sposA + lr) * 4);
            uint32_t b0A = lds32(wb0);
            uint32_t b1A = lds32(wb0 + W2STRIDE * 4);
            uint32_t b0B = lds32(wb0 + 32);
            uint32_t b1B = lds32(wb0 + W2STRIDE * 4 + 32);
            mma_tf32(dgA[g], za[g][0], za[g][1], za[g][2], za[g][3], b0A, b1A);
            mma_tf32(dgB[g], za[g][0], za[g][1], za[g][2], za[g][3], b0B, b1B);
        }

        // epilogue: h = hlane+{0,1} from A cols {0,1}, hlane+{2,3} from B cols {0,1}
        float hn_lo[4], cn_lo[4], hn_hi[4], cn_hi[4];
        {
            float ca_lo[4] = {cva.x, cva.y, cva.z, cva.w};
            float ca_hi[4] = {cvb.x, cvb.y, cvb.z, cvb.w};
            #pragma unroll
            for (int t = 0; t < 4; t++) {
                const int jc = t & 1;
                float (*dgX)[4] = (t < 2) ? dgA : dgB;
                {
                    float ig = sigm_fast(dgX[0][jc]);
                    float fg = sigm_fast(dgX[1][jc]);
                    float og = sigm_fast(dgX[2][jc]);
                    float gg = sigm_fast(dgX[3][jc]);
                    float cj = fmaf(fg, ca_lo[t], ig * gg);
                    cn_lo[t] = cj;
                    hn_lo[t] = og * tanh_fast(cj);
                }
                {
                    float ig = sigm_fast(dgX[0][jc + 2]);
                    float fg = sigm_fast(dgX[1][jc + 2]);
                    float og = sigm_fast(dgX[2][jc + 2]);
                    float gg = sigm_fast(dgX[3][jc + 2]);
                    float cj = fmaf(fg, ca_hi[t], ig * gg);
                    cn_hi[t] = cj;
                    hn_hi[t] = og * tanh_fast(cj);
                }
            }
        }
        *(float4*)(ho + hlane)              = make_float4(hn_lo[0], hn_lo[1], hn_lo[2], hn_lo[3]);
        *(float4*)(ho + 8 * HID_SZ + hlane) = make_float4(hn_hi[0], hn_hi[1], hn_hi[2], hn_hi[3]);
        *(float4*)(co + hlane)              = make_float4(cn_lo[0], cn_lo[1], cn_lo[2], cn_lo[3]);
        *(float4*)(co + 8 * HID_SZ + hlane) = make_float4(cn_hi[0], cn_hi[1], cn_hi[2], cn_hi[3]);
    }
}

extern "C" void kernel_launch(void* const* d_in, const int* in_sizes, int n_in,
                              void* d_out, int out_size) {
    const float* x  = (const float*)d_in[0];
    const float* h  = (const float*)d_in[1];
    const float* c  = (const float*)d_in[2];
    const float* W1 = (const float*)d_in[3];
    const float* b1 = (const float*)d_in[4];
    const float* W2 = (const float*)d_in[5];
    const float* b2 = (const float*)d_in[6];
    float* out = (float*)d_out;

    prep_kernel<<<200, 256>>>(W1, W2, b2);   // 51200 threads: 32768 W1 + 16384 W2 + 2048 b2

    cudaFuncSetAttribute(lstm_kernel, cudaFuncAttributeMaxDynamicSharedMemorySize, SMEM_TOTAL);
    lstm_kernel<<<NBLK, THREADS, SMEM_TOTAL>>>(x, h, c, b1, out);
}